// round 3
// baseline (speedup 1.0000x reference)
#include <cuda_runtime.h>

#define PATCH 32
#define MAXP  65536
#define NREAL 3

// Scratch (no allocations allowed)
__device__ float g_w[MAXP * 2];      // top-2 softmax scores per patch
__device__ int   g_meta[MAXP];       // i0 | i1<<8 | lvl<<16
__device__ int   g_start[MAXP];      // exclusive scan of counts
__device__ int   g_bsum[256];        // per-256-patch block sums

// ---------------------------------------------------------------------------
// Kernel 1: gate + per-block count sum. One THREAD per patch. Dot reduction in
// the same butterfly tree order as the original shfl version -> bit-identical
// logits -> identical routing -> identical T. (Do not touch.)
// ---------------------------------------------------------------------------
__global__ void gate_kernel(const float4* __restrict__ x4,
                            const float* __restrict__ Wg, int P) {
    __shared__ float wg[4 * PATCH];
    __shared__ int wsum[8];
    int t = threadIdx.x;
    if (t < 128) wg[t] = Wg[t];
    __syncthreads();

    int p = blockIdx.x * 256 + t;
    int lvl = 0;
    if (p < P) {
        float xv[32];
#pragma unroll
        for (int q = 0; q < 8; q++) {
            float4 v = x4[(long)p * 8 + q];
            xv[q * 4 + 0] = v.x; xv[q * 4 + 1] = v.y;
            xv[q * 4 + 2] = v.z; xv[q * 4 + 3] = v.w;
        }
        float lgt[4];
#pragma unroll
        for (int e = 0; e < 4; e++) {
            float a[32];
#pragma unroll
            for (int j = 0; j < 32; j++) a[j] = xv[j] * wg[e * 32 + j];
#pragma unroll
            for (int off = 16; off >= 1; off >>= 1)
#pragma unroll
                for (int i = 0; i < off; i++) a[i] += a[i + off];
            lgt[e] = a[0];
        }
        float m = fmaxf(fmaxf(lgt[0], lgt[1]), fmaxf(lgt[2], lgt[3]));
        float e4[4], s = 0.f;
#pragma unroll
        for (int i = 0; i < 4; i++) { e4[i] = expf(lgt[i] - m); s += e4[i]; }
        float inv = 1.f / s;
        float sc[4];
#pragma unroll
        for (int i = 0; i < 4; i++) sc[i] = e4[i] * inv;
        int i0 = 0;
#pragma unroll
        for (int i = 1; i < 4; i++) if (sc[i] > sc[i0]) i0 = i;
        int i1 = -1;
#pragma unroll
        for (int i = 0; i < 4; i++)
            if (i != i0 && (i1 < 0 || sc[i] > sc[i1])) i1 = i;
        int lv = -1;
        if (i0 < NREAL) lv = max(lv, i0);
        if (i1 < NREAL) lv = max(lv, i1);
        lvl = max(lv, 0);
        g_w[p * 2 + 0] = sc[i0];
        g_w[p * 2 + 1] = sc[i1];
        g_meta[p] = i0 | (i1 << 8) | (lvl << 16);
    }
    int cnt = (p < P) ? (1 << lvl) : 0;
    int ws = __reduce_add_sync(0xffffffffu, cnt);
    if ((t & 31) == 0) wsum[t >> 5] = ws;
    __syncthreads();
    if (t == 0) {
        int sum = 0;
#pragma unroll
        for (int i = 0; i < 8; i++) sum += wsum[i];
        g_bsum[blockIdx.x] = sum;
    }
}

// ---------------------------------------------------------------------------
// Kernel 2: per-patch starts. Each block redundantly reduces the block sums
// preceding it (<=1KB from L2), then does an intra-block shfl scan.
// ---------------------------------------------------------------------------
__global__ void starts_kernel(int P) {
    __shared__ int ws[8];
    __shared__ int bofs;
    int t = threadIdx.x, lane = t & 31, wp = t >> 5;
    int p = blockIdx.x * 256 + t;

    // block offset = sum of g_bsum[0..bid)
    int bo = (t < blockIdx.x) ? g_bsum[t] : 0;
    bo = __reduce_add_sync(0xffffffffu, bo);
    if (lane == 0) ws[wp] = bo;
    __syncthreads();
    if (t == 0) {
        int s = 0;
#pragma unroll
        for (int i = 0; i < 8; i++) s += ws[i];
        bofs = s;
    }
    __syncthreads();

    int cnt = (p < P) ? (1 << ((g_meta[p] >> 16) & 3)) : 0;
    int inc = cnt;
#pragma unroll
    for (int o = 1; o < 32; o <<= 1) {
        int u = __shfl_up_sync(0xffffffffu, inc, o);
        if (lane >= o) inc += u;
    }
    __syncthreads();           // ws reuse
    if (lane == 31) ws[wp] = inc;
    __syncthreads();
    if (wp == 0) {
        int s = (lane < 8) ? ws[lane] : 0;
#pragma unroll
        for (int o = 1; o < 8; o <<= 1) {
            int u = __shfl_up_sync(0xffffffffu, s, o);
            if (lane >= o) s += u;
        }
        if (lane < 8) ws[lane] = s;
    }
    __syncthreads();
    int off = wp ? ws[wp - 1] : 0;
    if (p < P) g_start[p] = bofs + off + inc - cnt;
}

// ---------------------------------------------------------------------------
// Kernel 3: writer, fully float4-vectorized. ONE WARP per patch.
// Lane mapping: c = lane>>3 (child), q = lane&7 (quad of 4 floats).
// All section boundaries are multiples of 4 floats -> whole-quad predicates.
// Output layout (floats):
//   [0,32T) new_x   [32T,64T) new_mask  [64T,65T) new_size
//   [65T,67T) weights  [67T,69T) expert_idx  [69T,165T) x_final [T,3,32]
// ALIGNED: x_final base (69T floats) is 16B-aligned iff T%4==0.
// ---------------------------------------------------------------------------
template <bool ALIGNED>
__global__ void write_kernel(const float4* __restrict__ x4,
                             const float4* __restrict__ m4,
                             float* __restrict__ out, int P, long T) {
    int w = (blockIdx.x * blockDim.x + threadIdx.x) >> 5;
    int lane = threadIdx.x & 31;
    if (w >= P) return;
    int c = lane >> 3, q = lane & 7;

    int meta  = g_meta[w];
    int start = g_start[w];
    int i0 = meta & 255, i1 = (meta >> 8) & 255, lvl = (meta >> 16) & 3;
    int cnt = 1 << lvl, sz = 32 >> lvl;
    bool active = c < cnt;

    const float4* xp = x4 + (long)w * 8;
    const float4* mp = m4 + (long)w * 8;
    float4 xq = xp[q];                 // quad q of this patch (L1 broadcast)
    float4 mq = mp[q];
    float4 pm = make_float4(xq.x * mq.x, xq.y * mq.y, xq.z * mq.z, xq.w * mq.w);
    const float4 z4 = make_float4(0.f, 0.f, 0.f, 0.f);

    // --- new_x / new_mask: child c, quad q -> source quad (c*sz + 4q)/4 ---
    bool qv = (q * 4) < sz;            // whole quad valid (sz multiple of 4)
    int gi = qv ? ((c * sz) >> 2) + q : 0;
    float4 gx = xp[gi];
    float4 gm = mp[gi];
    if (!qv) { gx = z4; gm = z4; }
    float4* out4 = (float4*)out;
    long idx4 = (long)(start + c) * 8 + q;
    if (active) {
        out4[idx4] = gx;
        out4[T * 8 + idx4] = gm;
    }

    // --- x_final: 3 levels; value = on ? x*m : 0, whole-quad predicate ---
    int j0 = q * 4;
    int lo_own = c * sz,              hi_own = lo_own + sz;
    int lo_par = (c >> 1) * (sz * 2), hi_par = lo_par + sz * 2;
#pragma unroll
    for (int l = 0; l < 3; l++) {
        bool on = (l == lvl)               ? (j0 >= lo_own && j0 < hi_own)
                : (lvl >= 1 && l == lvl-1) ? (j0 >= lo_par && j0 < hi_par)
                : false;
        float4 v = on ? pm : z4;
        long fo = (long)(start + c) * 24 + l * 8 + q;   // in float4 units
        if (active) {
            if (ALIGNED) {
                ((float4*)(out + T * 69))[fo] = v;
            } else {
                float* d = out + T * 69 + fo * 4;
                d[0] = v.x; d[1] = v.y; d[2] = v.z; d[3] = v.w;
            }
        }
    }

    // --- small fields ---
    if (lane < cnt) out[T * 64 + start + lane] = (float)sz;
    if (lane < cnt * 2) {
        int cc = lane >> 1, k = lane & 1;
        float wv = k ? g_w[w * 2 + 1] : g_w[w * 2];
        out[T * 65 + (long)(start + cc) * 2 + k] = wv;
        out[T * 67 + (long)(start + cc) * 2 + k] = (float)(k ? i1 : i0);
    }
}

// ---------------------------------------------------------------------------
extern "C" void kernel_launch(void* const* d_in, const int* in_sizes, int n_in,
                              void* d_out, int out_size) {
    const float* x    = (const float*)d_in[0];
    const float* mask = (const float*)d_in[1];
    const float* Wg   = (const float*)d_in[2];
    float* out = (float*)d_out;

    int n = in_sizes[0];
    int P = n / PATCH;                 // 65536
    long T = out_size / 165;

    int NB = (P + 255) / 256;          // 256
    gate_kernel<<<NB, 256>>>((const float4*)x, Wg, P);
    starts_kernel<<<NB, 256>>>(P);
    int wb = (P * 32 + 255) / 256;
    if ((T & 3) == 0)
        write_kernel<true><<<wb, 256>>>((const float4*)x, (const float4*)mask,
                                        out, P, T);
    else
        write_kernel<false><<<wb, 256>>>((const float4*)x, (const float4*)mask,
                                         out, P, T);
}

// round 4
// speedup vs baseline: 1.2857x; 1.2857x over previous
#include <cuda_runtime.h>

#define PATCH 32
#define MAXP  65536
#define NREAL 3

// Scratch (no allocations allowed)
__device__ float g_w[MAXP * 2];      // top-2 softmax scores per patch
__device__ int   g_meta[MAXP];       // i0 | i1<<8 | lvl<<16
__device__ int   g_start[MAXP];      // exclusive scan of counts
__device__ int   g_bsum[1024];       // per-64-patch block sums

// ---------------------------------------------------------------------------
// Kernel 1: gate, 4 THREADS per patch (quad). Each thread holds 8 elements.
// Reduction tree is bit-identical to the original butterfly (stages 16,8 via
// shfl_xor — fp add is commutative so partner order is safe — then 4,2,1
// in-thread). 64 patches per 256-thread block -> 1024 blocks, full occupancy.
// ---------------------------------------------------------------------------
__global__ void gate_kernel(const float4* __restrict__ x4,
                            const float* __restrict__ Wg, int P) {
    __shared__ float wg[4 * PATCH];
    __shared__ int wsum[8];
    int t = threadIdx.x;
    if (t < 128) wg[t] = Wg[t];
    __syncthreads();

    int gp = blockIdx.x * 64 + (t >> 2);   // patch id
    int qt = t & 3;                        // thread-in-quad
    int lvl = 0;
    int leader = (qt == 0);

    if (gp < P) {
        float xv[8];
        float4 v0 = x4[(long)gp * 8 + qt * 2];
        float4 v1 = x4[(long)gp * 8 + qt * 2 + 1];
        xv[0] = v0.x; xv[1] = v0.y; xv[2] = v0.z; xv[3] = v0.w;
        xv[4] = v1.x; xv[5] = v1.y; xv[6] = v1.z; xv[7] = v1.w;

        float lgt[4];
#pragma unroll
        for (int e = 0; e < 4; e++) {
            float p[8];
#pragma unroll
            for (int k = 0; k < 8; k++) p[k] = xv[k] * wg[e * 32 + qt * 8 + k];
            // stage 16: partner qt^2
            float a[8];
#pragma unroll
            for (int k = 0; k < 8; k++)
                a[k] = p[k] + __shfl_xor_sync(0xffffffffu, p[k], 2);
            // stage 8: partner qt^1
            float b[8];
#pragma unroll
            for (int k = 0; k < 8; k++)
                b[k] = a[k] + __shfl_xor_sync(0xffffffffu, a[k], 1);
            // in-thread stages 4,2,1
            float c0 = b[0] + b[4], c1 = b[1] + b[5];
            float c2 = b[2] + b[6], c3 = b[3] + b[7];
            float d0 = c0 + c2, d1 = c1 + c3;
            lgt[e] = d0 + d1;
        }
        if (leader) {
            float m = fmaxf(fmaxf(lgt[0], lgt[1]), fmaxf(lgt[2], lgt[3]));
            float e4[4], s = 0.f;
#pragma unroll
            for (int i = 0; i < 4; i++) { e4[i] = expf(lgt[i] - m); s += e4[i]; }
            float inv = 1.f / s;
            float sc[4];
#pragma unroll
            for (int i = 0; i < 4; i++) sc[i] = e4[i] * inv;
            int i0 = 0;
#pragma unroll
            for (int i = 1; i < 4; i++) if (sc[i] > sc[i0]) i0 = i;
            int i1 = -1;
#pragma unroll
            for (int i = 0; i < 4; i++)
                if (i != i0 && (i1 < 0 || sc[i] > sc[i1])) i1 = i;
            int lv = -1;
            if (i0 < NREAL) lv = max(lv, i0);
            if (i1 < NREAL) lv = max(lv, i1);
            lvl = max(lv, 0);
            g_w[gp * 2 + 0] = sc[i0];
            g_w[gp * 2 + 1] = sc[i1];
            g_meta[gp] = i0 | (i1 << 8) | (lvl << 16);
        }
    }
    int cnt = (leader && gp < P) ? (1 << lvl) : 0;
    int ws = __reduce_add_sync(0xffffffffu, cnt);
    if ((t & 31) == 0) wsum[t >> 5] = ws;
    __syncthreads();
    if (t == 0) {
        int sum = 0;
#pragma unroll
        for (int i = 0; i < 8; i++) sum += wsum[i];
        g_bsum[blockIdx.x] = sum;
    }
}

// ---------------------------------------------------------------------------
// Kernel 2: per-patch starts. Block offset = sum of the (4*bid) preceding
// 64-patch block sums, then intra-block shfl scan over 256 patches.
// ---------------------------------------------------------------------------
__global__ void starts_kernel(int P) {
    __shared__ int ws[8];
    __shared__ int bofs;
    int t = threadIdx.x, lane = t & 31, wp = t >> 5;
    int p = blockIdx.x * 256 + t;

    int lim = blockIdx.x * 4;           // preceding g_bsum entries
    int bo = 0;
    for (int i = t; i < lim; i += 256) bo += g_bsum[i];
    bo = __reduce_add_sync(0xffffffffu, bo);
    if (lane == 0) ws[wp] = bo;
    __syncthreads();
    if (t == 0) {
        int s = 0;
#pragma unroll
        for (int i = 0; i < 8; i++) s += ws[i];
        bofs = s;
    }
    __syncthreads();

    int cnt = (p < P) ? (1 << ((g_meta[p] >> 16) & 3)) : 0;
    int inc = cnt;
#pragma unroll
    for (int o = 1; o < 32; o <<= 1) {
        int u = __shfl_up_sync(0xffffffffu, inc, o);
        if (lane >= o) inc += u;
    }
    __syncthreads();
    if (lane == 31) ws[wp] = inc;
    __syncthreads();
    if (wp == 0) {
        int s = (lane < 8) ? ws[lane] : 0;
#pragma unroll
        for (int o = 1; o < 8; o <<= 1) {
            int u = __shfl_up_sync(0xffffffffu, s, o);
            if (lane >= o) s += u;
        }
        if (lane < 8) ws[lane] = s;
    }
    __syncthreads();
    int off = wp ? ws[wp - 1] : 0;
    if (p < P) g_start[p] = bofs + off + inc - cnt;
}

// ---------------------------------------------------------------------------
// Kernel 3: writer, ONE WARP per patch, lvl-specialized with compile-time
// lane predicates and immediate store offsets. Every store is a single fully
// coalesced 128B wavefront (base + const*32 + lane). No alignment assumptions.
// Output layout (floats):
//   [0,32T) new_x   [32T,64T) new_mask  [64T,65T) new_size
//   [65T,67T) weights  [67T,69T) expert_idx  [69T,165T) x_final [T,3,32]
// ---------------------------------------------------------------------------
__global__ void write_kernel(const float* __restrict__ x,
                             const float* __restrict__ mask,
                             float* __restrict__ out, int P, unsigned T) {
    unsigned w = (blockIdx.x * blockDim.x + threadIdx.x) >> 5;
    unsigned lane = threadIdx.x & 31;
    if (w >= (unsigned)P) return;

    float xv = x[w * 32u + lane];
    float mv = mask[w * 32u + lane];
    int meta = g_meta[w];
    unsigned start = (unsigned)g_start[w];
    int i0 = meta & 255, i1 = (meta >> 8) & 255, lvl = (meta >> 16) & 3;
    float pm = xv * mv;

    float* px = out + start * 32u + lane;       // new_x
    float* pk = px + T * 32u;                   // new_mask
    float* pf = out + T * 69u + start * 96u + lane;   // x_final
    float* ps = out + T * 64u + start;          // new_size
    float* pw = out + T * 65u + start * 2u + lane;    // weights (lane-flat)
    float* pe = out + T * 67u + start * 2u + lane;    // expert ids

    switch (lvl) {
    case 0: {   // cnt=1, sz=32
        px[0] = xv;  pk[0] = mv;
        pf[0] = pm;  pf[32] = 0.f;  pf[64] = 0.f;
        if (lane == 0) ps[0] = 32.f;
        if (lane < 2) {
            pw[0] = (lane & 1) ? g_w[w * 2 + 1] : g_w[w * 2];
            pe[0] = (float)((lane & 1) ? i1 : i0);
        }
        break;
    }
    case 1: {   // cnt=2, sz=16
        float x1 = __shfl_sync(0xffffffffu, xv, (16 + lane) & 31);
        float m1 = __shfl_sync(0xffffffffu, mv, (16 + lane) & 31);
        bool lo = lane < 16, hi = !lo;
        px[0]  = lo ? xv : 0.f;  pk[0]  = lo ? mv : 0.f;
        px[32] = lo ? x1 : 0.f;  pk[32] = lo ? m1 : 0.f;
        // child 0: l0 parent=all, l1 own=[0,16), l2=0
        pf[0]  = pm;            pf[32]  = lo ? pm : 0.f;  pf[64]  = 0.f;
        // child 1: l0 parent=all, l1 own=[16,32), l2=0
        pf[96] = pm;            pf[128] = hi ? pm : 0.f;  pf[160] = 0.f;
        if (lane < 2) ps[lane] = 16.f;
        if (lane < 4) {
            pw[0] = (lane & 1) ? g_w[w * 2 + 1] : g_w[w * 2];
            pe[0] = (float)((lane & 1) ? i1 : i0);
        }
        break;
    }
    default: {  // lvl=2: cnt=4, sz=8
        float xa = __shfl_sync(0xffffffffu, xv, (8  + lane) & 31);
        float ma = __shfl_sync(0xffffffffu, mv, (8  + lane) & 31);
        float xb = __shfl_sync(0xffffffffu, xv, (16 + lane) & 31);
        float mb = __shfl_sync(0xffffffffu, mv, (16 + lane) & 31);
        float xc = __shfl_sync(0xffffffffu, xv, (24 + lane) & 31);
        float mc = __shfl_sync(0xffffffffu, mv, (24 + lane) & 31);
        bool v8 = lane < 8;
        px[0]  = v8 ? xv : 0.f;  pk[0]  = v8 ? mv : 0.f;
        px[32] = v8 ? xa : 0.f;  pk[32] = v8 ? ma : 0.f;
        px[64] = v8 ? xb : 0.f;  pk[64] = v8 ? mb : 0.f;
        px[96] = v8 ? xc : 0.f;  pk[96] = v8 ? mc : 0.f;
        bool h0 = lane < 16, h1 = !h0;
        bool o0 = lane < 8, o1 = (lane >= 8) & h0;
        bool o2 = (lane >= 16) & (lane < 24), o3 = lane >= 24;
        // child c: l0=0, l1=parent half, l2=own eighth
        pf[0]   = 0.f;  pf[32]  = h0 ? pm : 0.f;  pf[64]  = o0 ? pm : 0.f;
        pf[96]  = 0.f;  pf[128] = h0 ? pm : 0.f;  pf[160] = o1 ? pm : 0.f;
        pf[192] = 0.f;  pf[224] = h1 ? pm : 0.f;  pf[256] = o2 ? pm : 0.f;
        pf[288] = 0.f;  pf[320] = h1 ? pm : 0.f;  pf[352] = o3 ? pm : 0.f;
        if (lane < 4) ps[lane] = 8.f;
        if (lane < 8) {
            pw[0] = (lane & 1) ? g_w[w * 2 + 1] : g_w[w * 2];
            pe[0] = (float)((lane & 1) ? i1 : i0);
        }
        break;
    }
    }
}

// ---------------------------------------------------------------------------
extern "C" void kernel_launch(void* const* d_in, const int* in_sizes, int n_in,
                              void* d_out, int out_size) {
    const float* x    = (const float*)d_in[0];
    const float* mask = (const float*)d_in[1];
    const float* Wg   = (const float*)d_in[2];
    float* out = (float*)d_out;

    int n = in_sizes[0];
    int P = n / PATCH;                 // 65536
    unsigned T = (unsigned)(out_size / 165);

    int NBg = (P + 63) / 64;           // 1024 gate blocks (64 patches each)
    gate_kernel<<<NBg, 256>>>((const float4*)x, Wg, P);
    int NBs = (P + 255) / 256;         // 256
    starts_kernel<<<NBs, 256>>>(P);
    write_kernel<<<(P * 32 + 255) / 256, 256>>>(x, mask, out, P, T);
}